// round 13
// baseline (speedup 1.0000x reference)
#include <cuda_runtime.h>
#include <cuda_fp16.h>
#include <math.h>
#include <stdint.h>

#define DMODEL 1024
#define NHEADS 16
#define HDIM   64
#define BATCH  2
#define SEQ    2048
#define NQT    (SEQ / 64)

// ---------------- scratch (no allocations allowed) ----------------
__device__ __half g_xq[BATCH * SEQ * DMODEL];
__device__ __half g_xk[BATCH * SEQ * DMODEL];
__device__ __half g_xv[BATCH * SEQ * DMODEL];
__device__ __half g_whk[DMODEL * DMODEL];
__device__ __half g_whv[DMODEL * DMODEL];
__device__ __half g_who[DMODEL * DMODEL];
__device__ __half g_qp[BATCH * SEQ * DMODEL];
__device__ __half g_kp[BATCH * SEQ * DMODEL];
__device__ __half g_vp[BATCH * SEQ * DMODEL];
__device__ __half g_ctx[BATCH * SEQ * DMODEL];
__device__ __half g_ew[(size_t)BATCH * NHEADS * SEQ * SEQ];  // unnormalized exp (fp16)

__device__ __forceinline__ uint32_t smem_u32(const void* p) {
    uint32_t a;
    asm("{ .reg .u64 t; cvta.to.shared.u64 t, %1; cvt.u32.u64 %0, t; }"
        : "=r"(a) : "l"(p));
    return a;
}
__device__ __forceinline__ uint32_t pack2(float a, float b) {
    __half2 h = __floats2half2_rn(a, b);
    return *(uint32_t*)&h;
}
__device__ __forceinline__ uint4 ldsm4(uint32_t addr) {
    uint4 r;
    asm volatile("ldmatrix.sync.aligned.m8n8.x4.shared.b16 {%0,%1,%2,%3}, [%4];"
                 : "=r"(r.x), "=r"(r.y), "=r"(r.z), "=r"(r.w) : "r"(addr));
    return r;
}
__device__ __forceinline__ uint4 ldsm4t(uint32_t addr) {
    uint4 r;
    asm volatile("ldmatrix.sync.aligned.m8n8.x4.trans.shared.b16 {%0,%1,%2,%3}, [%4];"
                 : "=r"(r.x), "=r"(r.y), "=r"(r.z), "=r"(r.w) : "r"(addr));
    return r;
}
__device__ __forceinline__ void mma16(float* d, const uint4& a, uint32_t b0, uint32_t b1) {
    asm volatile(
        "mma.sync.aligned.m16n8k16.row.col.f32.f16.f16.f32 "
        "{%0,%1,%2,%3},{%4,%5,%6,%7},{%8,%9},{%0,%1,%2,%3};"
        : "+f"(d[0]), "+f"(d[1]), "+f"(d[2]), "+f"(d[3])
        : "r"(a.x), "r"(a.y), "r"(a.z), "r"(a.w), "r"(b0), "r"(b1));
}
#define CP16(dst, src) \
    asm volatile("cp.async.cg.shared.global [%0], [%1], 16;" :: "r"(dst), "l"(src))
#define CP_COMMIT() asm volatile("cp.async.commit_group;" ::: "memory")
#define CP_WAIT0()  asm volatile("cp.async.wait_group 0;" ::: "memory")
#define CP_WAIT1()  asm volatile("cp.async.wait_group 1;" ::: "memory")

// ================================================================
// fp32 -> fp16 convert (3 tensors per launch, equal sizes)
// ================================================================
__global__ __launch_bounds__(256)
void conv_f2h(const float* __restrict__ s0, const float* __restrict__ s1,
              const float* __restrict__ s2, __half* __restrict__ d0,
              __half* __restrict__ d1, __half* __restrict__ d2)
{
    const float* s = blockIdx.y == 0 ? s0 : (blockIdx.y == 1 ? s1 : s2);
    __half*      d = blockIdx.y == 0 ? d0 : (blockIdx.y == 1 ? d1 : d2);
    int i = (blockIdx.x * 256 + threadIdx.x) * 4;
    float4 v = *(const float4*)(s + i);
    *(uint2*)(d + i) = make_uint2(pack2(v.x, v.y), pack2(v.z, v.w));
}

// ================================================================
// fp16 GEMM core: C[128,128] = X @ W^T + bias
// BK=32, 3-stage cp.async pipeline, one sync per k-tile.
// smem pitch 40 halves (80B): conflict-free ldmatrix; stage=20480B
// ================================================================
#define GNKT (DMODEL / 32)
#define GSTAGE 20480
#define GEMM_SMEM (3 * GSTAGE)

template <bool HOUT>
__device__ __forceinline__ void gemm_core_f16(
    const __half* __restrict__ X, const __half* __restrict__ Wt,
    const float* __restrict__ bias, void* __restrict__ Cv,
    int bm, int bn, __half* smem)
{
    const uint32_t sb = smem_u32(smem);
    const int tid = threadIdx.x, lane = tid & 31, wid = tid >> 5;
    const int wm = (wid & 1) * 64, wn = (wid >> 1) * 32;
    const int g = lane >> 2, t = lane & 3;

    float acc[4][4][4];
    #pragma unroll
    for (int mt = 0; mt < 4; mt++)
      #pragma unroll
      for (int nt = 0; nt < 4; nt++)
        #pragma unroll
        for (int i = 0; i < 4; i++) acc[mt][nt][i] = 0.f;

    const int fr = tid >> 1, fc = (tid & 1) * 16;
    const __half* xs0 = X  + (size_t)(bm + fr) * DMODEL + fc;
    const __half* ws0 = Wt + (size_t)(bn + fr) * DMODEL + fc;
    const uint32_t doff = (fr * 40 + fc) * 2;

    // prologue: stages 0,1
    #pragma unroll
    for (int s = 0; s < 2; ++s) {
        uint32_t ad = sb + s * GSTAGE + doff, bd = ad + 10240;
        CP16(ad, xs0 + s * 32); CP16(ad + 16, xs0 + s * 32 + 8);
        CP16(bd, ws0 + s * 32); CP16(bd + 16, ws0 + s * 32 + 8);
        CP_COMMIT();
    }

    const uint32_t afroff = ((wm + (lane & 15)) * 40 + (lane >> 4) * 8) * 2;
    const uint32_t bfroff = ((wn + (lane & 15)) * 40 + (lane >> 4) * 8) * 2 + 10240;

    int stg = 0;
    #pragma unroll 1
    for (int kt = 0; kt < GNKT; ++kt) {
        if (kt + 1 < GNKT) { CP_WAIT1(); } else { CP_WAIT0(); }
        __syncthreads();   // also protects stage reuse (3-deep ring)
        if (kt + 2 < GNKT) {
            int ns = stg + 2; if (ns >= 3) ns -= 3;
            uint32_t ad = sb + ns * GSTAGE + doff, bd = ad + 10240;
            const __half* xs = xs0 + (kt + 2) * 32;
            const __half* ws = ws0 + (kt + 2) * 32;
            CP16(ad, xs); CP16(ad + 16, xs + 8);
            CP16(bd, ws); CP16(bd + 16, ws + 8);
            CP_COMMIT();
        }
        const uint32_t abase = sb + stg * GSTAGE;
        const uint32_t afr = abase + afroff;
        const uint32_t bfr = abase + bfroff;
        #pragma unroll
        for (int ks = 0; ks < 2; ++ks) {
            uint4 b0 = ldsm4(bfr + ks * 32);
            uint4 b1 = ldsm4(bfr + 16 * 80 + ks * 32);
            #pragma unroll
            for (int mt = 0; mt < 4; ++mt) {
                uint4 a = ldsm4(afr + mt * 16 * 80 + ks * 32);
                mma16(acc[mt][0], a, b0.x, b0.z);
                mma16(acc[mt][1], a, b0.y, b0.w);
                mma16(acc[mt][2], a, b1.x, b1.z);
                mma16(acc[mt][3], a, b1.y, b1.w);
            }
        }
        stg = (stg + 1 == 3) ? 0 : stg + 1;
    }

    #pragma unroll
    for (int mt = 0; mt < 4; mt++) {
        int r0 = bm + wm + mt * 16 + g;
        #pragma unroll
        for (int nt = 0; nt < 4; nt++) {
            int c = bn + wn + nt * 8 + 2 * t;
            float2 bb = *(const float2*)(bias + c);
            float o00 = acc[mt][nt][0] + bb.x, o01 = acc[mt][nt][1] + bb.y;
            float o10 = acc[mt][nt][2] + bb.x, o11 = acc[mt][nt][3] + bb.y;
            if (HOUT) {
                __half* C = (__half*)Cv;
                *(uint32_t*)(C + (size_t)r0 * DMODEL + c)       = pack2(o00, o01);
                *(uint32_t*)(C + (size_t)(r0 + 8) * DMODEL + c) = pack2(o10, o11);
            } else {
                float* C = (float*)Cv;
                *(float2*)(C + (size_t)r0 * DMODEL + c)       = make_float2(o00, o01);
                *(float2*)(C + (size_t)(r0 + 8) * DMODEL + c) = make_float2(o10, o11);
            }
        }
    }
}

// all three projections in one launch (q,k use Wk — ref bug; v uses Wv)
__global__ __launch_bounds__(256, 2)
void gemm_qkv(const __half* __restrict__ xq, const __half* __restrict__ xk,
              const __half* __restrict__ xv, const __half* __restrict__ whk,
              const __half* __restrict__ whv, const float* __restrict__ bk,
              const float* __restrict__ bv, __half* __restrict__ qp,
              __half* __restrict__ kp, __half* __restrict__ vp)
{
    extern __shared__ __half sm[];
    const int sel = blockIdx.y >> 5;
    const int bm = (blockIdx.y & 31) * 128, bn = blockIdx.x * 128;
    const __half* X = sel == 0 ? xq : (sel == 1 ? xk : xv);
    const __half* W = sel == 2 ? whv : whk;
    const float*  B = sel == 2 ? bv : bk;
    __half*       O = sel == 0 ? qp : (sel == 1 ? kp : vp);
    gemm_core_f16<true>(X, W, B, O, bm, bn, sm);
}

__global__ __launch_bounds__(256, 2)
void gemm_o(const __half* __restrict__ X, const __half* __restrict__ wh,
            const float* __restrict__ bias, float* __restrict__ C)
{
    extern __shared__ __half sm[];
    gemm_core_f16<false>(X, wh, bias, C, blockIdx.y * 128, blockIdx.x * 128, sm);
}

// ================================================================
// Fused causal attention + normalization. Block = 128q x 64k tiles.
// Main loop: e -> fp16 scratch g_ew (+smem P). Tail: scratch -> w fp32.
// ================================================================
#define SK0 9216
#define SK1 13824
#define SV0 18432
#define SV1 23040
#define SP  27648
#define ATTN_SMEM (73728 + 256 * 4)

__global__ __launch_bounds__(256, 2)
void attn_h(const __half* __restrict__ qp, const __half* __restrict__ kp,
            const __half* __restrict__ vp, float* __restrict__ w,
            __half* __restrict__ ctx, __half* __restrict__ ew)
{
    extern __shared__ __half hs[];
    float* rsum_sm = (float*)(hs + 36864);
    float* invsm   = rsum_sm + 128;

    const int qt = 15 - (int)blockIdx.x;
    const int h = blockIdx.y, b = blockIdx.z;
    const int q0 = qt * 128;
    const int nkt = 2 * qt + 2;
    const int tid = threadIdx.x, lane = tid & 31, wid = tid >> 5;
    const int wm = (wid & 3) * 32, wn = (wid >> 2) * 32;
    const int g = lane >> 2, t = lane & 3;
    const uint32_t sb = smem_u32(hs);

    if (tid < 128) rsum_sm[tid] = 0.f;

    const uint32_t qfr = sb + (((wm + (lane & 15)) * 72 + (lane >> 4) * 8) << 1);
    const uint32_t pfr = sb + ((SP + (wm + (lane & 15)) * 72 + (lane >> 4) * 8) << 1);
    const uint32_t kfroff = (((wn + (lane & 15)) * 72 + (lane >> 4) * 8) << 1);
    const uint32_t vfroff = (((lane & 15) * 72 + wn + (lane >> 4) * 8) << 1);

    const int qr = tid >> 1, qc = (tid & 1) * 32;
    const int kr = tid >> 2, kc = (tid & 3) * 16;
    const __half* ksrc0 = kp + (size_t)(b * SEQ + kr) * DMODEL + h * HDIM + kc;
    const __half* vsrc0 = vp + (size_t)(b * SEQ + kr) * DMODEL + h * HDIM + kc;

    {
        uint32_t qd = sb + ((qr * 72 + qc) << 1);
        const __half* qs = qp + (size_t)(b * SEQ + q0 + qr) * DMODEL + h * HDIM + qc;
        CP16(qd, qs); CP16(qd + 16, qs + 8); CP16(qd + 32, qs + 16); CP16(qd + 48, qs + 24);
        uint32_t kd = sb + ((SK0 + kr * 72 + kc) << 1);
        uint32_t vd = sb + ((SV0 + kr * 72 + kc) << 1);
        CP16(kd, ksrc0); CP16(kd + 16, ksrc0 + 8);
        CP16(vd, vsrc0); CP16(vd + 16, vsrc0 + 8);
        CP_COMMIT();
    }

    float cacc[2][4][4];
    #pragma unroll
    for (int m = 0; m < 2; m++)
      #pragma unroll
      for (int nt = 0; nt < 4; nt++)
        #pragma unroll
        for (int i = 0; i < 4; i++) cacc[m][nt][i] = 0.f;
    float rs[2][2] = {{0.f, 0.f}, {0.f, 0.f}};

    float*  wbase  = w  + (size_t)((b * NHEADS + h) * SEQ) * SEQ;
    __half* ewbase = ew + (size_t)((b * NHEADS + h) * SEQ) * SEQ;

    for (int kt = 0; kt < nkt; ++kt) {
        CP_WAIT0();
        __syncthreads();
        const int buf = kt & 1;

        if (kt + 1 < nkt) {
            const int nb = buf ^ 1;
            uint32_t kd = sb + (((nb ? SK1 : SK0) + kr * 72 + kc) << 1);
            uint32_t vd = sb + (((nb ? SV1 : SV0) + kr * 72 + kc) << 1);
            const __half* ks = ksrc0 + (size_t)(kt + 1) * 64 * DMODEL;
            const __half* vs = vsrc0 + (size_t)(kt + 1) * 64 * DMODEL;
            CP16(kd, ks); CP16(kd + 16, ks + 8);
            CP16(vd, vs); CP16(vd + 16, vs + 8);
            CP_COMMIT();
        }

        const uint32_t kfr = sb + (((buf ? SK1 : SK0)) << 1) + kfroff;
        const uint32_t vfr = sb + (((buf ? SV1 : SV0)) << 1) + vfroff;

        // GEMM1: S = Q K^T
        float s[2][4][4];
        #pragma unroll
        for (int m = 0; m < 2; m++)
          #pragma unroll
          for (int nt = 0; nt < 4; nt++)
            #pragma unroll
            for (int i = 0; i < 4; i++) s[m][nt][i] = 0.f;
        #pragma unroll
        for (int kd = 0; kd < 64; kd += 16) {
            uint4 a0 = ldsm4(qfr + (kd << 1));
            uint4 a1 = ldsm4(qfr + ((16 * 72 + kd) << 1));
            #pragma unroll
            for (int nb = 0; nb < 2; ++nb) {
                uint4 bf = ldsm4(kfr + ((nb * 16 * 72 + kd) << 1));
                mma16(s[0][nb * 2],     a0, bf.x, bf.z);
                mma16(s[0][nb * 2 + 1], a0, bf.y, bf.w);
                mma16(s[1][nb * 2],     a1, bf.x, bf.z);
                mma16(s[1][nb * 2 + 1], a1, bf.y, bf.w);
            }
        }

        // exp, mask, rowsums; store e fp16 to scratch + smem P
        const int k0 = kt * 64;
        #pragma unroll
        for (int m = 0; m < 2; m++) {
            const int r0g = q0 + wm + m * 16 + g, r1g = r0g + 8;
            #pragma unroll
            for (int nt = 0; nt < 4; nt++) {
                int ck = k0 + wn + nt * 8 + 2 * t;
                float e00 = __expf(s[m][nt][0] * 0.125f); if (ck     > r0g) e00 = 0.f;
                float e01 = __expf(s[m][nt][1] * 0.125f); if (ck + 1 > r0g) e01 = 0.f;
                float e10 = __expf(s[m][nt][2] * 0.125f); if (ck     > r1g) e10 = 0.f;
                float e11 = __expf(s[m][nt][3] * 0.125f); if (ck + 1 > r1g) e11 = 0.f;
                rs[m][0] += e00 + e01;
                rs[m][1] += e10 + e11;
                uint32_t p0 = pack2(e00, e01), p1 = pack2(e10, e11);
                *(uint32_t*)(ewbase + (size_t)r0g * SEQ + ck) = p0;
                *(uint32_t*)(ewbase + (size_t)r1g * SEQ + ck) = p1;
                int pc = wn + nt * 8 + 2 * t;
                *(uint32_t*)(hs + SP + (wm + m * 16 + g) * 72 + pc)     = p0;
                *(uint32_t*)(hs + SP + (wm + m * 16 + g + 8) * 72 + pc) = p1;
            }
        }
        __syncthreads();

        // GEMM2: ctx += P V
        #pragma unroll
        for (int kk = 0; kk < 64; kk += 16) {
            uint4 a0 = ldsm4(pfr + (kk << 1));
            uint4 a1 = ldsm4(pfr + ((16 * 72 + kk) << 1));
            #pragma unroll
            for (int nb = 0; nb < 2; ++nb) {
                uint4 bf = ldsm4t(vfr + ((kk * 72 + nb * 16) << 1));
                mma16(cacc[0][nb * 2],     a0, bf.x, bf.y);
                mma16(cacc[0][nb * 2 + 1], a0, bf.z, bf.w);
                mma16(cacc[1][nb * 2],     a1, bf.x, bf.y);
                mma16(cacc[1][nb * 2 + 1], a1, bf.z, bf.w);
            }
        }
    }

    // rowsum reduce -> invsm
    #pragma unroll
    for (int m = 0; m < 2; m++)
      #pragma unroll
      for (int hf = 0; hf < 2; hf++) {
          rs[m][hf] += __shfl_xor_sync(0xffffffffu, rs[m][hf], 1);
          rs[m][hf] += __shfl_xor_sync(0xffffffffu, rs[m][hf], 2);
      }
    if (t == 0) {
        atomicAdd(&rsum_sm[wm + g],          rs[0][0]);
        atomicAdd(&rsum_sm[wm + g + 8],      rs[0][1]);
        atomicAdd(&rsum_sm[wm + 16 + g],     rs[1][0]);
        atomicAdd(&rsum_sm[wm + 16 + g + 8], rs[1][1]);
    }
    __syncthreads();
    if (tid < 128) invsm[tid] = 1.0f / rsum_sm[tid];
    __syncthreads();

    // store normalized ctx (fp16) in concat layout
    #pragma unroll
    for (int m = 0; m < 2; m++) {
        float iv0 = invsm[wm + m * 16 + g], iv1 = invsm[wm + m * 16 + g + 8];
        int r0 = q0 + wm + m * 16 + g;
        #pragma unroll
        for (int nt = 0; nt < 4; nt++) {
            int c = h * HDIM + wn + nt * 8 + 2 * t;
            *(uint32_t*)(ctx + (size_t)(b * SEQ + r0) * DMODEL + c) =
                pack2(cacc[m][nt][0] * iv0, cacc[m][nt][1] * iv0);
            *(uint32_t*)(ctx + (size_t)(b * SEQ + r0 + 8) * DMODEL + c) =
                pack2(cacc[m][nt][2] * iv1, cacc[m][nt][3] * iv1);
        }
    }

    // tail: zero-fill masked region of w; normalize scratch -> w fp32
    {
        const int tcol = tid & 15, trow = tid >> 4;
        for (int kt2 = nkt; kt2 < NQT; ++kt2) {
            int k0 = kt2 * 64;
            #pragma unroll
            for (int rr = 0; rr < 8; ++rr) {
                int row = q0 + trow + rr * 16;
                *(float4*)(wbase + (size_t)row * SEQ + k0 + tcol * 4) =
                    make_float4(0.f, 0.f, 0.f, 0.f);
            }
        }
        for (int kt2 = 0; kt2 < nkt; ++kt2) {
            int k0 = kt2 * 64;
            #pragma unroll
            for (int rr = 0; rr < 8; ++rr) {
                int row = trow + rr * 16;
                float iv = invsm[row];
                uint2 hv = *(uint2*)(ewbase + (size_t)(q0 + row) * SEQ + k0 + tcol * 4);
                __half2 ha = *(__half2*)&hv.x, hb = *(__half2*)&hv.y;
                float2 fa = __half22float2(ha), fb = __half22float2(hb);
                *(float4*)(wbase + (size_t)(q0 + row) * SEQ + k0 + tcol * 4) =
                    make_float4(fa.x * iv, fa.y * iv, fb.x * iv, fb.y * iv);
            }
        }
    }
}

// ================================================================
// launch
// ================================================================
extern "C" void kernel_launch(void* const* d_in, const int* in_sizes, int n_in,
                              void* d_out, int out_size)
{
    const float* query = (const float*)d_in[0];
    const float* key   = (const float*)d_in[1];
    const float* value = (const float*)d_in[2];
    const float* Wk = (const float*)d_in[4];
    const float* bk = (const float*)d_in[5];
    const float* Wv = (const float*)d_in[6];
    const float* bv = (const float*)d_in[7];
    const float* Wo = (const float*)d_in[8];
    const float* bo = (const float*)d_in[9];

    float* out = (float*)d_out;
    float* w   = out + (size_t)BATCH * SEQ * DMODEL;

    __half *xq, *xk, *xv, *whk, *whv, *who, *qp, *kp, *vp, *ctx, *ew;
    cudaGetSymbolAddress((void**)&xq,  g_xq);
    cudaGetSymbolAddress((void**)&xk,  g_xk);
    cudaGetSymbolAddress((void**)&xv,  g_xv);
    cudaGetSymbolAddress((void**)&whk, g_whk);
    cudaGetSymbolAddress((void**)&whv, g_whv);
    cudaGetSymbolAddress((void**)&who, g_who);
    cudaGetSymbolAddress((void**)&qp,  g_qp);
    cudaGetSymbolAddress((void**)&kp,  g_kp);
    cudaGetSymbolAddress((void**)&vp,  g_vp);
    cudaGetSymbolAddress((void**)&ctx, g_ctx);
    cudaGetSymbolAddress((void**)&ew,  g_ew);

    cudaFuncSetAttribute(attn_h, cudaFuncAttributeMaxDynamicSharedMemorySize,
                         ATTN_SMEM);
    cudaFuncSetAttribute(gemm_qkv, cudaFuncAttributeMaxDynamicSharedMemorySize,
                         GEMM_SMEM);
    cudaFuncSetAttribute(gemm_o, cudaFuncAttributeMaxDynamicSharedMemorySize,
                         GEMM_SMEM);

    conv_f2h<<<dim3((BATCH * SEQ * DMODEL) / 1024, 3), 256>>>(
        query, key, value, xq, xk, xv);
    conv_f2h<<<dim3((DMODEL * DMODEL) / 1024, 3), 256>>>(
        Wk, Wv, Wo, whk, whv, who);

    gemm_qkv<<<dim3(8, 96), 256, GEMM_SMEM>>>(
        xq, xk, xv, whk, whv, bk, bv, qp, kp, vp);

    attn_h<<<dim3(16, NHEADS, BATCH), 256, ATTN_SMEM>>>(qp, kp, vp, w, ctx, ew);

    gemm_o<<<dim3(8, 32), 256, GEMM_SMEM>>>(ctx, who, bo, out);
}

// round 14
// speedup vs baseline: 1.3345x; 1.3345x over previous
#include <cuda_runtime.h>
#include <cuda_fp16.h>
#include <math.h>
#include <stdint.h>

#define DMODEL 1024
#define NHEADS 16
#define HDIM   64
#define BATCH  2
#define SEQ    2048
#define NQT    (SEQ / 64)

// ---------------- scratch (no allocations allowed) ----------------
__device__ __half g_xq[BATCH * SEQ * DMODEL];
__device__ __half g_xk[BATCH * SEQ * DMODEL];
__device__ __half g_xv[BATCH * SEQ * DMODEL];
__device__ __half g_whk[DMODEL * DMODEL];
__device__ __half g_whv[DMODEL * DMODEL];
__device__ __half g_who[DMODEL * DMODEL];
__device__ __half g_qp[BATCH * SEQ * DMODEL];
__device__ __half g_kp[BATCH * SEQ * DMODEL];
__device__ __half g_vp[BATCH * SEQ * DMODEL];
__device__ __half g_ctx[BATCH * SEQ * DMODEL];

__device__ __forceinline__ uint32_t smem_u32(const void* p) {
    uint32_t a;
    asm("{ .reg .u64 t; cvta.to.shared.u64 t, %1; cvt.u32.u64 %0, t; }"
        : "=r"(a) : "l"(p));
    return a;
}
__device__ __forceinline__ uint32_t pack2(float a, float b) {
    __half2 h = __floats2half2_rn(a, b);
    return *(uint32_t*)&h;
}
__device__ __forceinline__ uint4 ldsm4(uint32_t addr) {
    uint4 r;
    asm volatile("ldmatrix.sync.aligned.m8n8.x4.shared.b16 {%0,%1,%2,%3}, [%4];"
                 : "=r"(r.x), "=r"(r.y), "=r"(r.z), "=r"(r.w) : "r"(addr));
    return r;
}
__device__ __forceinline__ uint4 ldsm4t(uint32_t addr) {
    uint4 r;
    asm volatile("ldmatrix.sync.aligned.m8n8.x4.trans.shared.b16 {%0,%1,%2,%3}, [%4];"
                 : "=r"(r.x), "=r"(r.y), "=r"(r.z), "=r"(r.w) : "r"(addr));
    return r;
}
__device__ __forceinline__ void mma16(float* d, const uint4& a, uint32_t b0, uint32_t b1) {
    asm volatile(
        "mma.sync.aligned.m16n8k16.row.col.f32.f16.f16.f32 "
        "{%0,%1,%2,%3},{%4,%5,%6,%7},{%8,%9},{%0,%1,%2,%3};"
        : "+f"(d[0]), "+f"(d[1]), "+f"(d[2]), "+f"(d[3])
        : "r"(a.x), "r"(a.y), "r"(a.z), "r"(a.w), "r"(b0), "r"(b1));
}
#define CP16(dst, src) \
    asm volatile("cp.async.cg.shared.global [%0], [%1], 16;" :: "r"(dst), "l"(src))
#define CP_COMMIT() asm volatile("cp.async.commit_group;" ::: "memory")
#define CP_WAIT0()  asm volatile("cp.async.wait_group 0;" ::: "memory")
#define CP_WAIT1()  asm volatile("cp.async.wait_group 1;" ::: "memory")

// ================================================================
// fp32 -> fp16 convert (3 tensors per launch, equal sizes)
// ================================================================
__global__ __launch_bounds__(256)
void conv_f2h(const float* __restrict__ s0, const float* __restrict__ s1,
              const float* __restrict__ s2, __half* __restrict__ d0,
              __half* __restrict__ d1, __half* __restrict__ d2)
{
    const float* s = blockIdx.y == 0 ? s0 : (blockIdx.y == 1 ? s1 : s2);
    __half*      d = blockIdx.y == 0 ? d0 : (blockIdx.y == 1 ? d1 : d2);
    int i = (blockIdx.x * 256 + threadIdx.x) * 4;
    float4 v = *(const float4*)(s + i);
    *(uint2*)(d + i) = make_uint2(pack2(v.x, v.y), pack2(v.z, v.w));
}

// ================================================================
// fp16 GEMM core: C[128,128] = X @ W^T + bias
// BK=32, 3-stage cp.async pipeline, one sync per k-tile. (R13, proven)
// ================================================================
#define GNKT (DMODEL / 32)
#define GSTAGE 20480
#define GEMM_SMEM (3 * GSTAGE)

template <bool HOUT>
__device__ __forceinline__ void gemm_core_f16(
    const __half* __restrict__ X, const __half* __restrict__ Wt,
    const float* __restrict__ bias, void* __restrict__ Cv,
    int bm, int bn, __half* smem)
{
    const uint32_t sb = smem_u32(smem);
    const int tid = threadIdx.x, lane = tid & 31, wid = tid >> 5;
    const int wm = (wid & 1) * 64, wn = (wid >> 1) * 32;
    const int g = lane >> 2, t = lane & 3;

    float acc[4][4][4];
    #pragma unroll
    for (int mt = 0; mt < 4; mt++)
      #pragma unroll
      for (int nt = 0; nt < 4; nt++)
        #pragma unroll
        for (int i = 0; i < 4; i++) acc[mt][nt][i] = 0.f;

    const int fr = tid >> 1, fc = (tid & 1) * 16;
    const __half* xs0 = X  + (size_t)(bm + fr) * DMODEL + fc;
    const __half* ws0 = Wt + (size_t)(bn + fr) * DMODEL + fc;
    const uint32_t doff = (fr * 40 + fc) * 2;

    #pragma unroll
    for (int s = 0; s < 2; ++s) {
        uint32_t ad = sb + s * GSTAGE + doff, bd = ad + 10240;
        CP16(ad, xs0 + s * 32); CP16(ad + 16, xs0 + s * 32 + 8);
        CP16(bd, ws0 + s * 32); CP16(bd + 16, ws0 + s * 32 + 8);
        CP_COMMIT();
    }

    const uint32_t afroff = ((wm + (lane & 15)) * 40 + (lane >> 4) * 8) * 2;
    const uint32_t bfroff = ((wn + (lane & 15)) * 40 + (lane >> 4) * 8) * 2 + 10240;

    int stg = 0;
    #pragma unroll 1
    for (int kt = 0; kt < GNKT; ++kt) {
        if (kt + 1 < GNKT) { CP_WAIT1(); } else { CP_WAIT0(); }
        __syncthreads();
        if (kt + 2 < GNKT) {
            int ns = stg + 2; if (ns >= 3) ns -= 3;
            uint32_t ad = sb + ns * GSTAGE + doff, bd = ad + 10240;
            const __half* xs = xs0 + (kt + 2) * 32;
            const __half* ws = ws0 + (kt + 2) * 32;
            CP16(ad, xs); CP16(ad + 16, xs + 8);
            CP16(bd, ws); CP16(bd + 16, ws + 8);
            CP_COMMIT();
        }
        const uint32_t abase = sb + stg * GSTAGE;
        const uint32_t afr = abase + afroff;
        const uint32_t bfr = abase + bfroff;
        #pragma unroll
        for (int ks = 0; ks < 2; ++ks) {
            uint4 b0 = ldsm4(bfr + ks * 32);
            uint4 b1 = ldsm4(bfr + 16 * 80 + ks * 32);
            #pragma unroll
            for (int mt = 0; mt < 4; ++mt) {
                uint4 a = ldsm4(afr + mt * 16 * 80 + ks * 32);
                mma16(acc[mt][0], a, b0.x, b0.z);
                mma16(acc[mt][1], a, b0.y, b0.w);
                mma16(acc[mt][2], a, b1.x, b1.z);
                mma16(acc[mt][3], a, b1.y, b1.w);
            }
        }
        stg = (stg + 1 == 3) ? 0 : stg + 1;
    }

    #pragma unroll
    for (int mt = 0; mt < 4; mt++) {
        int r0 = bm + wm + mt * 16 + g;
        #pragma unroll
        for (int nt = 0; nt < 4; nt++) {
            int c = bn + wn + nt * 8 + 2 * t;
            float2 bb = *(const float2*)(bias + c);
            float o00 = acc[mt][nt][0] + bb.x, o01 = acc[mt][nt][1] + bb.y;
            float o10 = acc[mt][nt][2] + bb.x, o11 = acc[mt][nt][3] + bb.y;
            if (HOUT) {
                __half* C = (__half*)Cv;
                *(uint32_t*)(C + (size_t)r0 * DMODEL + c)       = pack2(o00, o01);
                *(uint32_t*)(C + (size_t)(r0 + 8) * DMODEL + c) = pack2(o10, o11);
            } else {
                float* C = (float*)Cv;
                *(float2*)(C + (size_t)r0 * DMODEL + c)       = make_float2(o00, o01);
                *(float2*)(C + (size_t)(r0 + 8) * DMODEL + c) = make_float2(o10, o11);
            }
        }
    }
}

// all three projections in one launch (q,k use Wk — ref bug; v uses Wv)
__global__ __launch_bounds__(256, 2)
void gemm_qkv(const __half* __restrict__ xq, const __half* __restrict__ xk,
              const __half* __restrict__ xv, const __half* __restrict__ whk,
              const __half* __restrict__ whv, const float* __restrict__ bk,
              const float* __restrict__ bv, __half* __restrict__ qp,
              __half* __restrict__ kp, __half* __restrict__ vp)
{
    extern __shared__ __half sm[];
    const int sel = blockIdx.y >> 5;
    const int bm = (blockIdx.y & 31) * 128, bn = blockIdx.x * 128;
    const __half* X = sel == 0 ? xq : (sel == 1 ? xk : xv);
    const __half* W = sel == 2 ? whv : whk;
    const float*  B = sel == 2 ? bv : bk;
    __half*       O = sel == 0 ? qp : (sel == 1 ? kp : vp);
    gemm_core_f16<true>(X, W, B, O, bm, bn, sm);
}

__global__ __launch_bounds__(256, 2)
void gemm_o(const __half* __restrict__ X, const __half* __restrict__ wh,
            const float* __restrict__ bias, float* __restrict__ C)
{
    extern __shared__ __half sm[];
    gemm_core_f16<false>(X, wh, bias, C, blockIdx.y * 128, blockIdx.x * 128, sm);
}

// ================================================================
// Fused causal attention + normalization (R10 version, proven fast).
// Block = 128q x 64k tiles; w written fp32 unnormalized in mainloop;
// tail: zero-fill masked region + in-place RMW normalize own rows.
// ================================================================
#define SK0 9216
#define SK1 13824
#define SV0 18432
#define SV1 23040
#define SP  27648
#define ATTN_SMEM (73728 + 256 * 4)

__global__ __launch_bounds__(256, 2)
void attn_h(const __half* __restrict__ qp, const __half* __restrict__ kp,
            const __half* __restrict__ vp, float* __restrict__ w,
            __half* __restrict__ ctx)
{
    extern __shared__ __half hs[];
    float* rsum_sm = (float*)(hs + 36864);
    float* invsm   = rsum_sm + 128;

    const int qt = 15 - (int)blockIdx.x;      // big tiles first
    const int h = blockIdx.y, b = blockIdx.z;
    const int q0 = qt * 128;
    const int nkt = 2 * qt + 2;
    const int tid = threadIdx.x, lane = tid & 31, wid = tid >> 5;
    const int wm = (wid & 3) * 32, wn = (wid >> 2) * 32;
    const int g = lane >> 2, t = lane & 3;
    const uint32_t sb = smem_u32(hs);

    if (tid < 128) rsum_sm[tid] = 0.f;

    const uint32_t qfr = sb + (((wm + (lane & 15)) * 72 + (lane >> 4) * 8) << 1);
    const uint32_t pfr = sb + ((SP + (wm + (lane & 15)) * 72 + (lane >> 4) * 8) << 1);
    const uint32_t kfroff = (((wn + (lane & 15)) * 72 + (lane >> 4) * 8) << 1);
    const uint32_t vfroff = (((lane & 15) * 72 + wn + (lane >> 4) * 8) << 1);

    const int qr = tid >> 1, qc = (tid & 1) * 32;
    const int kr = tid >> 2, kc = (tid & 3) * 16;
    const __half* ksrc0 = kp + (size_t)(b * SEQ + kr) * DMODEL + h * HDIM + kc;
    const __half* vsrc0 = vp + (size_t)(b * SEQ + kr) * DMODEL + h * HDIM + kc;

    {
        uint32_t qd = sb + ((qr * 72 + qc) << 1);
        const __half* qs = qp + (size_t)(b * SEQ + q0 + qr) * DMODEL + h * HDIM + qc;
        CP16(qd, qs); CP16(qd + 16, qs + 8); CP16(qd + 32, qs + 16); CP16(qd + 48, qs + 24);
        uint32_t kd = sb + ((SK0 + kr * 72 + kc) << 1);
        uint32_t vd = sb + ((SV0 + kr * 72 + kc) << 1);
        CP16(kd, ksrc0); CP16(kd + 16, ksrc0 + 8);
        CP16(vd, vsrc0); CP16(vd + 16, vsrc0 + 8);
        CP_COMMIT();
    }

    float cacc[2][4][4];
    #pragma unroll
    for (int m = 0; m < 2; m++)
      #pragma unroll
      for (int nt = 0; nt < 4; nt++)
        #pragma unroll
        for (int i = 0; i < 4; i++) cacc[m][nt][i] = 0.f;
    float rs[2][2] = {{0.f, 0.f}, {0.f, 0.f}};

    float* wbase = w + (size_t)((b * NHEADS + h) * SEQ) * SEQ;

    for (int kt = 0; kt < nkt; ++kt) {
        CP_WAIT0();
        __syncthreads();
        const int buf = kt & 1;

        if (kt + 1 < nkt) {
            const int nb = buf ^ 1;
            uint32_t kd = sb + (((nb ? SK1 : SK0) + kr * 72 + kc) << 1);
            uint32_t vd = sb + (((nb ? SV1 : SV0) + kr * 72 + kc) << 1);
            const __half* ks = ksrc0 + (size_t)(kt + 1) * 64 * DMODEL;
            const __half* vs = vsrc0 + (size_t)(kt + 1) * 64 * DMODEL;
            CP16(kd, ks); CP16(kd + 16, ks + 8);
            CP16(vd, vs); CP16(vd + 16, vs + 8);
            CP_COMMIT();
        }

        const uint32_t kfr = sb + (((buf ? SK1 : SK0)) << 1) + kfroff;
        const uint32_t vfr = sb + (((buf ? SV1 : SV0)) << 1) + vfroff;

        // GEMM1: S = Q K^T
        float s[2][4][4];
        #pragma unroll
        for (int m = 0; m < 2; m++)
          #pragma unroll
          for (int nt = 0; nt < 4; nt++)
            #pragma unroll
            for (int i = 0; i < 4; i++) s[m][nt][i] = 0.f;
        #pragma unroll
        for (int kd = 0; kd < 64; kd += 16) {
            uint4 a0 = ldsm4(qfr + (kd << 1));
            uint4 a1 = ldsm4(qfr + ((16 * 72 + kd) << 1));
            #pragma unroll
            for (int nb = 0; nb < 2; ++nb) {
                uint4 bf = ldsm4(kfr + ((nb * 16 * 72 + kd) << 1));
                mma16(s[0][nb * 2],     a0, bf.x, bf.z);
                mma16(s[0][nb * 2 + 1], a0, bf.y, bf.w);
                mma16(s[1][nb * 2],     a1, bf.x, bf.z);
                mma16(s[1][nb * 2 + 1], a1, bf.y, bf.w);
            }
        }

        // exp, mask, write unnormalized w (fp32), rowsums, stage P
        const int k0 = kt * 64;
        #pragma unroll
        for (int m = 0; m < 2; m++) {
            const int r0g = q0 + wm + m * 16 + g, r1g = r0g + 8;
            #pragma unroll
            for (int nt = 0; nt < 4; nt++) {
                int ck = k0 + wn + nt * 8 + 2 * t;
                float e00 = __expf(s[m][nt][0] * 0.125f); if (ck     > r0g) e00 = 0.f;
                float e01 = __expf(s[m][nt][1] * 0.125f); if (ck + 1 > r0g) e01 = 0.f;
                float e10 = __expf(s[m][nt][2] * 0.125f); if (ck     > r1g) e10 = 0.f;
                float e11 = __expf(s[m][nt][3] * 0.125f); if (ck + 1 > r1g) e11 = 0.f;
                rs[m][0] += e00 + e01;
                rs[m][1] += e10 + e11;
                *(float2*)(wbase + (size_t)r0g * SEQ + ck) = make_float2(e00, e01);
                *(float2*)(wbase + (size_t)r1g * SEQ + ck) = make_float2(e10, e11);
                int pc = wn + nt * 8 + 2 * t;
                *(uint32_t*)(hs + SP + (wm + m * 16 + g) * 72 + pc)     = pack2(e00, e01);
                *(uint32_t*)(hs + SP + (wm + m * 16 + g + 8) * 72 + pc) = pack2(e10, e11);
            }
        }
        __syncthreads();

        // GEMM2: ctx += P V
        #pragma unroll
        for (int kk = 0; kk < 64; kk += 16) {
            uint4 a0 = ldsm4(pfr + (kk << 1));
            uint4 a1 = ldsm4(pfr + ((16 * 72 + kk) << 1));
            #pragma unroll
            for (int nb = 0; nb < 2; ++nb) {
                uint4 bf = ldsm4t(vfr + ((kk * 72 + nb * 16) << 1));
                mma16(cacc[0][nb * 2],     a0, bf.x, bf.y);
                mma16(cacc[0][nb * 2 + 1], a0, bf.z, bf.w);
                mma16(cacc[1][nb * 2],     a1, bf.x, bf.y);
                mma16(cacc[1][nb * 2 + 1], a1, bf.z, bf.w);
            }
        }
    }

    // rowsum reduce -> invsm
    #pragma unroll
    for (int m = 0; m < 2; m++)
      #pragma unroll
      for (int hf = 0; hf < 2; hf++) {
          rs[m][hf] += __shfl_xor_sync(0xffffffffu, rs[m][hf], 1);
          rs[m][hf] += __shfl_xor_sync(0xffffffffu, rs[m][hf], 2);
      }
    if (t == 0) {
        atomicAdd(&rsum_sm[wm + g],          rs[0][0]);
        atomicAdd(&rsum_sm[wm + g + 8],      rs[0][1]);
        atomicAdd(&rsum_sm[wm + 16 + g],     rs[1][0]);
        atomicAdd(&rsum_sm[wm + 16 + g + 8], rs[1][1]);
    }
    __syncthreads();
    if (tid < 128) invsm[tid] = 1.0f / rsum_sm[tid];
    __syncthreads();

    // store normalized ctx (fp16) in concat layout [b, s, h*64+d]
    #pragma unroll
    for (int m = 0; m < 2; m++) {
        float iv0 = invsm[wm + m * 16 + g], iv1 = invsm[wm + m * 16 + g + 8];
        int r0 = q0 + wm + m * 16 + g;
        #pragma unroll
        for (int nt = 0; nt < 4; nt++) {
            int c = h * HDIM + wn + nt * 8 + 2 * t;
            *(uint32_t*)(ctx + (size_t)(b * SEQ + r0) * DMODEL + c) =
                pack2(cacc[m][nt][0] * iv0, cacc[m][nt][1] * iv0);
            *(uint32_t*)(ctx + (size_t)(b * SEQ + r0 + 8) * DMODEL + c) =
                pack2(cacc[m][nt][2] * iv1, cacc[m][nt][3] * iv1);
        }
    }

    // tail 1: zero-fill masked tiles of w
    {
        const int tcol = tid & 15, trow = tid >> 4;
        for (int kt2 = nkt; kt2 < NQT; ++kt2) {
            int k0 = kt2 * 64;
            #pragma unroll
            for (int rr = 0; rr < 8; ++rr) {
                int row = q0 + trow + rr * 16;
                *(float4*)(wbase + (size_t)row * SEQ + k0 + tcol * 4) =
                    make_float4(0.f, 0.f, 0.f, 0.f);
            }
        }
        // tail 2: normalize own w rows in place
        for (int kt2 = 0; kt2 < nkt; ++kt2) {
            int k0 = kt2 * 64;
            #pragma unroll
            for (int rr = 0; rr < 8; ++rr) {
                int row = trow + rr * 16;
                float iv = invsm[row];
                float4* p = (float4*)(wbase + (size_t)(q0 + row) * SEQ + k0 + tcol * 4);
                float4 v = *p;
                v.x *= iv; v.y *= iv; v.z *= iv; v.w *= iv;
                *p = v;
            }
        }
    }
}

// ================================================================
// launch
// ================================================================
extern "C" void kernel_launch(void* const* d_in, const int* in_sizes, int n_in,
                              void* d_out, int out_size)
{
    const float* query = (const float*)d_in[0];
    const float* key   = (const float*)d_in[1];
    const float* value = (const float*)d_in[2];
    const float* Wk = (const float*)d_in[4];
    const float* bk = (const float*)d_in[5];
    const float* Wv = (const float*)d_in[6];
    const float* bv = (const float*)d_in[7];
    const float* Wo = (const float*)d_in[8];
    const float* bo = (const float*)d_in[9];

    float* out = (float*)d_out;
    float* w   = out + (size_t)BATCH * SEQ * DMODEL;

    __half *xq, *xk, *xv, *whk, *whv, *who, *qp, *kp, *vp, *ctx;
    cudaGetSymbolAddress((void**)&xq,  g_xq);
    cudaGetSymbolAddress((void**)&xk,  g_xk);
    cudaGetSymbolAddress((void**)&xv,  g_xv);
    cudaGetSymbolAddress((void**)&whk, g_whk);
    cudaGetSymbolAddress((void**)&whv, g_whv);
    cudaGetSymbolAddress((void**)&who, g_who);
    cudaGetSymbolAddress((void**)&qp,  g_qp);
    cudaGetSymbolAddress((void**)&kp,  g_kp);
    cudaGetSymbolAddress((void**)&vp,  g_vp);
    cudaGetSymbolAddress((void**)&ctx, g_ctx);

    cudaFuncSetAttribute(attn_h, cudaFuncAttributeMaxDynamicSharedMemorySize,
                         ATTN_SMEM);
    cudaFuncSetAttribute(gemm_qkv, cudaFuncAttributeMaxDynamicSharedMemorySize,
                         GEMM_SMEM);
    cudaFuncSetAttribute(gemm_o, cudaFuncAttributeMaxDynamicSharedMemorySize,
                         GEMM_SMEM);

    conv_f2h<<<dim3((BATCH * SEQ * DMODEL) / 1024, 3), 256>>>(
        query, key, value, xq, xk, xv);
    conv_f2h<<<dim3((DMODEL * DMODEL) / 1024, 3), 256>>>(
        Wk, Wv, Wo, whk, whv, who);

    gemm_qkv<<<dim3(8, 96), 256, GEMM_SMEM>>>(
        xq, xk, xv, whk, whv, bk, bv, qp, kp, vp);

    attn_h<<<dim3(16, NHEADS, BATCH), 256, ATTN_SMEM>>>(qp, kp, vp, w, ctx);

    gemm_o<<<dim3(8, 32), 256, GEMM_SMEM>>>(ctx, who, bo, out);
}

// round 16
// speedup vs baseline: 1.4065x; 1.0539x over previous
#include <cuda_runtime.h>
#include <cuda_fp16.h>
#include <math.h>
#include <stdint.h>

#define DMODEL 1024
#define NHEADS 16
#define HDIM   64
#define BATCH  2
#define SEQ    2048
#define NQT    (SEQ / 64)

// ---------------- scratch (no allocations allowed) ----------------
__device__ __half g_xq[BATCH * SEQ * DMODEL];
__device__ __half g_xk[BATCH * SEQ * DMODEL];
__device__ __half g_xv[BATCH * SEQ * DMODEL];
__device__ __half g_whk[DMODEL * DMODEL];
__device__ __half g_whv[DMODEL * DMODEL];
__device__ __half g_who[DMODEL * DMODEL];
__device__ __half g_qp[BATCH * SEQ * DMODEL];
__device__ __half g_kp[BATCH * SEQ * DMODEL];
__device__ __half g_vp[BATCH * SEQ * DMODEL];
__device__ __half g_ctx[BATCH * SEQ * DMODEL];

__device__ __forceinline__ uint32_t smem_u32(const void* p) {
    uint32_t a;
    asm("{ .reg .u64 t; cvta.to.shared.u64 t, %1; cvt.u32.u64 %0, t; }"
        : "=r"(a) : "l"(p));
    return a;
}
__device__ __forceinline__ uint32_t pack2(float a, float b) {
    __half2 h = __floats2half2_rn(a, b);
    return *(uint32_t*)&h;
}
__device__ __forceinline__ uint4 ldsm4(uint32_t addr) {
    uint4 r;
    asm volatile("ldmatrix.sync.aligned.m8n8.x4.shared.b16 {%0,%1,%2,%3}, [%4];"
                 : "=r"(r.x), "=r"(r.y), "=r"(r.z), "=r"(r.w) : "r"(addr));
    return r;
}
__device__ __forceinline__ uint4 ldsm4t(uint32_t addr) {
    uint4 r;
    asm volatile("ldmatrix.sync.aligned.m8n8.x4.trans.shared.b16 {%0,%1,%2,%3}, [%4];"
                 : "=r"(r.x), "=r"(r.y), "=r"(r.z), "=r"(r.w) : "r"(addr));
    return r;
}
__device__ __forceinline__ void mma16(float* d, const uint4& a, uint32_t b0, uint32_t b1) {
    asm volatile(
        "mma.sync.aligned.m16n8k16.row.col.f32.f16.f16.f32 "
        "{%0,%1,%2,%3},{%4,%5,%6,%7},{%8,%9},{%0,%1,%2,%3};"
        : "+f"(d[0]), "+f"(d[1]), "+f"(d[2]), "+f"(d[3])
        : "r"(a.x), "r"(a.y), "r"(a.z), "r"(a.w), "r"(b0), "r"(b1));
}
#define CP16(dst, src) \
    asm volatile("cp.async.cg.shared.global [%0], [%1], 16;" :: "r"(dst), "l"(src))
#define CP_COMMIT() asm volatile("cp.async.commit_group;" ::: "memory")
#define CP_WAIT0()  asm volatile("cp.async.wait_group 0;" ::: "memory")
#define CP_WAIT1()  asm volatile("cp.async.wait_group 1;" ::: "memory")

// ================================================================
// fp32 -> fp16 convert (3 tensors per launch, equal sizes)
// ================================================================
__global__ __launch_bounds__(256)
void conv_f2h(const float* __restrict__ s0, const float* __restrict__ s1,
              const float* __restrict__ s2, __half* __restrict__ d0,
              __half* __restrict__ d1, __half* __restrict__ d2)
{
    const float* s = blockIdx.y == 0 ? s0 : (blockIdx.y == 1 ? s1 : s2);
    __half*      d = blockIdx.y == 0 ? d0 : (blockIdx.y == 1 ? d1 : d2);
    int i = (blockIdx.x * 256 + threadIdx.x) * 4;
    float4 v = *(const float4*)(s + i);
    *(uint2*)(d + i) = make_uint2(pack2(v.x, v.y), pack2(v.z, v.w));
}

// ================================================================
// fp16 GEMM core: C[128,128] = X @ W^T + bias  (R13/R14, proven)
// ================================================================
#define GNKT (DMODEL / 32)
#define GSTAGE 20480
#define GEMM_SMEM (3 * GSTAGE)

template <bool HOUT>
__device__ __forceinline__ void gemm_core_f16(
    const __half* __restrict__ X, const __half* __restrict__ Wt,
    const float* __restrict__ bias, void* __restrict__ Cv,
    int bm, int bn, __half* smem)
{
    const uint32_t sb = smem_u32(smem);
    const int tid = threadIdx.x, lane = tid & 31, wid = tid >> 5;
    const int wm = (wid & 1) * 64, wn = (wid >> 1) * 32;
    const int g = lane >> 2, t = lane & 3;

    float acc[4][4][4];
    #pragma unroll
    for (int mt = 0; mt < 4; mt++)
      #pragma unroll
      for (int nt = 0; nt < 4; nt++)
        #pragma unroll
        for (int i = 0; i < 4; i++) acc[mt][nt][i] = 0.f;

    const int fr = tid >> 1, fc = (tid & 1) * 16;
    const __half* xs0 = X  + (size_t)(bm + fr) * DMODEL + fc;
    const __half* ws0 = Wt + (size_t)(bn + fr) * DMODEL + fc;
    const uint32_t doff = (fr * 40 + fc) * 2;

    #pragma unroll
    for (int s = 0; s < 2; ++s) {
        uint32_t ad = sb + s * GSTAGE + doff, bd = ad + 10240;
        CP16(ad, xs0 + s * 32); CP16(ad + 16, xs0 + s * 32 + 8);
        CP16(bd, ws0 + s * 32); CP16(bd + 16, ws0 + s * 32 + 8);
        CP_COMMIT();
    }

    const uint32_t afroff = ((wm + (lane & 15)) * 40 + (lane >> 4) * 8) * 2;
    const uint32_t bfroff = ((wn + (lane & 15)) * 40 + (lane >> 4) * 8) * 2 + 10240;

    int stg = 0;
    #pragma unroll 1
    for (int kt = 0; kt < GNKT; ++kt) {
        if (kt + 1 < GNKT) { CP_WAIT1(); } else { CP_WAIT0(); }
        __syncthreads();
        if (kt + 2 < GNKT) {
            int ns = stg + 2; if (ns >= 3) ns -= 3;
            uint32_t ad = sb + ns * GSTAGE + doff, bd = ad + 10240;
            const __half* xs = xs0 + (kt + 2) * 32;
            const __half* ws = ws0 + (kt + 2) * 32;
            CP16(ad, xs); CP16(ad + 16, xs + 8);
            CP16(bd, ws); CP16(bd + 16, ws + 8);
            CP_COMMIT();
        }
        const uint32_t abase = sb + stg * GSTAGE;
        const uint32_t afr = abase + afroff;
        const uint32_t bfr = abase + bfroff;
        #pragma unroll
        for (int ks = 0; ks < 2; ++ks) {
            uint4 b0 = ldsm4(bfr + ks * 32);
            uint4 b1 = ldsm4(bfr + 16 * 80 + ks * 32);
            #pragma unroll
            for (int mt = 0; mt < 4; ++mt) {
                uint4 a = ldsm4(afr + mt * 16 * 80 + ks * 32);
                mma16(acc[mt][0], a, b0.x, b0.z);
                mma16(acc[mt][1], a, b0.y, b0.w);
                mma16(acc[mt][2], a, b1.x, b1.z);
                mma16(acc[mt][3], a, b1.y, b1.w);
            }
        }
        stg = (stg + 1 == 3) ? 0 : stg + 1;
    }

    #pragma unroll
    for (int mt = 0; mt < 4; mt++) {
        int r0 = bm + wm + mt * 16 + g;
        #pragma unroll
        for (int nt = 0; nt < 4; nt++) {
            int c = bn + wn + nt * 8 + 2 * t;
            float2 bb = *(const float2*)(bias + c);
            float o00 = acc[mt][nt][0] + bb.x, o01 = acc[mt][nt][1] + bb.y;
            float o10 = acc[mt][nt][2] + bb.x, o11 = acc[mt][nt][3] + bb.y;
            if (HOUT) {
                __half* C = (__half*)Cv;
                *(uint32_t*)(C + (size_t)r0 * DMODEL + c)       = pack2(o00, o01);
                *(uint32_t*)(C + (size_t)(r0 + 8) * DMODEL + c) = pack2(o10, o11);
            } else {
                float* C = (float*)Cv;
                *(float2*)(C + (size_t)r0 * DMODEL + c)       = make_float2(o00, o01);
                *(float2*)(C + (size_t)(r0 + 8) * DMODEL + c) = make_float2(o10, o11);
            }
        }
    }
}

// all three projections in one launch (q,k use Wk — ref bug; v uses Wv)
__global__ __launch_bounds__(256, 2)
void gemm_qkv(const __half* __restrict__ xq, const __half* __restrict__ xk,
              const __half* __restrict__ xv, const __half* __restrict__ whk,
              const __half* __restrict__ whv, const float* __restrict__ bk,
              const float* __restrict__ bv, __half* __restrict__ qp,
              __half* __restrict__ kp, __half* __restrict__ vp)
{
    extern __shared__ __half sm[];
    const int sel = blockIdx.y >> 5;
    const int bm = (blockIdx.y & 31) * 128, bn = blockIdx.x * 128;
    const __half* X = sel == 0 ? xq : (sel == 1 ? xk : xv);
    const __half* W = sel == 2 ? whv : whk;
    const float*  B = sel == 2 ? bv : bk;
    __half*       O = sel == 0 ? qp : (sel == 1 ? kp : vp);
    gemm_core_f16<true>(X, W, B, O, bm, bn, sm);
}

__global__ __launch_bounds__(256, 2)
void gemm_o(const __half* __restrict__ X, const __half* __restrict__ wh,
            const float* __restrict__ bias, float* __restrict__ C)
{
    extern __shared__ __half sm[];
    gemm_core_f16<false>(X, wh, bias, C, blockIdx.y * 128, blockIdx.x * 128, sm);
}

// ================================================================
// Fused causal attention, TWO-PASS (no w RMW):
//  zero-fill masked w region up front (streaming stores)
//  pass 1: S=QK^T, exp, rowsums only (K-only dbuf loads)
//  pass 2: recompute S, write NORMALIZED w (stcs), P normalized, PV
// ================================================================
#define SK0 9216
#define SK1 13824
#define SV0 18432
#define SV1 23040
#define SP  27648
#define ATTN_SMEM (73728 + 256 * 4)

__global__ __launch_bounds__(256, 2)
void attn_h(const __half* __restrict__ qp, const __half* __restrict__ kp,
            const __half* __restrict__ vp, float* __restrict__ w,
            __half* __restrict__ ctx)
{
    extern __shared__ __half hs[];
    float* rsum_sm = (float*)(hs + 36864);
    float* invsm   = rsum_sm + 128;

    const int qt = 15 - (int)blockIdx.x;      // big tiles first
    const int h = blockIdx.y, b = blockIdx.z;
    const int q0 = qt * 128;
    const int nkt = 2 * qt + 2;
    const int tid = threadIdx.x, lane = tid & 31, wid = tid >> 5;
    const int wm = (wid & 3) * 32, wn = (wid >> 2) * 32;
    const int g = lane >> 2, t = lane & 3;
    const uint32_t sb = smem_u32(hs);

    if (tid < 128) rsum_sm[tid] = 0.f;

    const uint32_t qfr = sb + (((wm + (lane & 15)) * 72 + (lane >> 4) * 8) << 1);
    const uint32_t pfr = sb + ((SP + (wm + (lane & 15)) * 72 + (lane >> 4) * 8) << 1);
    const uint32_t kfroff = (((wn + (lane & 15)) * 72 + (lane >> 4) * 8) << 1);
    const uint32_t vfroff = (((lane & 15) * 72 + wn + (lane >> 4) * 8) << 1);

    const int qr = tid >> 1, qc = (tid & 1) * 32;
    const int kr = tid >> 2, kc = (tid & 3) * 16;
    const __half* ksrc0 = kp + (size_t)(b * SEQ + kr) * DMODEL + h * HDIM + kc;
    const __half* vsrc0 = vp + (size_t)(b * SEQ + kr) * DMODEL + h * HDIM + kc;

    float* wbase = w + (size_t)((b * NHEADS + h) * SEQ) * SEQ;

    // prologue: Q + K tile 0 (pass 1 needs no V)
    {
        uint32_t qd = sb + ((qr * 72 + qc) << 1);
        const __half* qs = qp + (size_t)(b * SEQ + q0 + qr) * DMODEL + h * HDIM + qc;
        CP16(qd, qs); CP16(qd + 16, qs + 8); CP16(qd + 32, qs + 16); CP16(qd + 48, qs + 24);
        uint32_t kd = sb + ((SK0 + kr * 72 + kc) << 1);
        CP16(kd, ksrc0); CP16(kd + 16, ksrc0 + 8);
        CP_COMMIT();
    }

    // zero-fill masked w tiles now (stores drain while pass 1 computes)
    {
        const int tcol = tid & 15, trow = tid >> 4;
        for (int kt2 = nkt; kt2 < NQT; ++kt2) {
            int k0 = kt2 * 64;
            #pragma unroll
            for (int rr = 0; rr < 8; ++rr) {
                int row = q0 + trow + rr * 16;
                __stcs((float4*)(wbase + (size_t)row * SEQ + k0 + tcol * 4),
                       make_float4(0.f, 0.f, 0.f, 0.f));
            }
        }
    }

    float rs[2][2] = {{0.f, 0.f}, {0.f, 0.f}};

    // ================= PASS 1: rowsums only =================
    for (int kt = 0; kt < nkt; ++kt) {
        CP_WAIT0();
        __syncthreads();
        const int buf = kt & 1;
        if (kt + 1 < nkt) {
            const int nb = buf ^ 1;
            uint32_t kd = sb + (((nb ? SK1 : SK0) + kr * 72 + kc) << 1);
            const __half* ks = ksrc0 + (size_t)(kt + 1) * 64 * DMODEL;
            CP16(kd, ks); CP16(kd + 16, ks + 8);
            CP_COMMIT();
        }
        const uint32_t kfr = sb + (((buf ? SK1 : SK0)) << 1) + kfroff;

        float s[2][4][4];
        #pragma unroll
        for (int m = 0; m < 2; m++)
          #pragma unroll
          for (int nt = 0; nt < 4; nt++)
            #pragma unroll
            for (int i = 0; i < 4; i++) s[m][nt][i] = 0.f;
        #pragma unroll
        for (int kd = 0; kd < 64; kd += 16) {
            uint4 a0 = ldsm4(qfr + (kd << 1));
            uint4 a1 = ldsm4(qfr + ((16 * 72 + kd) << 1));
            #pragma unroll
            for (int nb = 0; nb < 2; ++nb) {
                uint4 bf = ldsm4(kfr + ((nb * 16 * 72 + kd) << 1));
                mma16(s[0][nb * 2],     a0, bf.x, bf.z);
                mma16(s[0][nb * 2 + 1], a0, bf.y, bf.w);
                mma16(s[1][nb * 2],     a1, bf.x, bf.z);
                mma16(s[1][nb * 2 + 1], a1, bf.y, bf.w);
            }
        }

        const int k0 = kt * 64;
        #pragma unroll
        for (int m = 0; m < 2; m++) {
            const int r0g = q0 + wm + m * 16 + g, r1g = r0g + 8;
            #pragma unroll
            for (int nt = 0; nt < 4; nt++) {
                int ck = k0 + wn + nt * 8 + 2 * t;
                float e00 = __expf(s[m][nt][0] * 0.125f); if (ck     > r0g) e00 = 0.f;
                float e01 = __expf(s[m][nt][1] * 0.125f); if (ck + 1 > r0g) e01 = 0.f;
                float e10 = __expf(s[m][nt][2] * 0.125f); if (ck     > r1g) e10 = 0.f;
                float e11 = __expf(s[m][nt][3] * 0.125f); if (ck + 1 > r1g) e11 = 0.f;
                rs[m][0] += e00 + e01;
                rs[m][1] += e10 + e11;
            }
        }
    }

    // rowsum reduce -> invsm
    #pragma unroll
    for (int m = 0; m < 2; m++)
      #pragma unroll
      for (int hf = 0; hf < 2; hf++) {
          rs[m][hf] += __shfl_xor_sync(0xffffffffu, rs[m][hf], 1);
          rs[m][hf] += __shfl_xor_sync(0xffffffffu, rs[m][hf], 2);
      }
    if (t == 0) {
        atomicAdd(&rsum_sm[wm + g],          rs[0][0]);
        atomicAdd(&rsum_sm[wm + g + 8],      rs[0][1]);
        atomicAdd(&rsum_sm[wm + 16 + g],     rs[1][0]);
        atomicAdd(&rsum_sm[wm + 16 + g + 8], rs[1][1]);
    }
    __syncthreads();
    if (tid < 128) invsm[tid] = 1.0f / rsum_sm[tid];
    __syncthreads();

    float ivr[2][2];
    #pragma unroll
    for (int m = 0; m < 2; m++) {
        ivr[m][0] = invsm[wm + m * 16 + g];
        ivr[m][1] = invsm[wm + m * 16 + g + 8];
    }

    float cacc[2][4][4];
    #pragma unroll
    for (int m = 0; m < 2; m++)
      #pragma unroll
      for (int nt = 0; nt < 4; nt++)
        #pragma unroll
        for (int i = 0; i < 4; i++) cacc[m][nt][i] = 0.f;

    // PASS 2 prologue: K0 + V0
    {
        uint32_t kd = sb + ((SK0 + kr * 72 + kc) << 1);
        uint32_t vd = sb + ((SV0 + kr * 72 + kc) << 1);
        CP16(kd, ksrc0); CP16(kd + 16, ksrc0 + 8);
        CP16(vd, vsrc0); CP16(vd + 16, vsrc0 + 8);
        CP_COMMIT();
    }

    // ================= PASS 2: write normalized w + PV =================
    for (int kt = 0; kt < nkt; ++kt) {
        CP_WAIT0();
        __syncthreads();
        const int buf = kt & 1;

        if (kt + 1 < nkt) {
            const int nb = buf ^ 1;
            uint32_t kd = sb + (((nb ? SK1 : SK0) + kr * 72 + kc) << 1);
            uint32_t vd = sb + (((nb ? SV1 : SV0) + kr * 72 + kc) << 1);
            const __half* ks = ksrc0 + (size_t)(kt + 1) * 64 * DMODEL;
            const __half* vs = vsrc0 + (size_t)(kt + 1) * 64 * DMODEL;
            CP16(kd, ks); CP16(kd + 16, ks + 8);
            CP16(vd, vs); CP16(vd + 16, vs + 8);
            CP_COMMIT();
        }

        const uint32_t kfr = sb + (((buf ? SK1 : SK0)) << 1) + kfroff;
        const uint32_t vfr = sb + (((buf ? SV1 : SV0)) << 1) + vfroff;

        float s[2][4][4];
        #pragma unroll
        for (int m = 0; m < 2; m++)
          #pragma unroll
          for (int nt = 0; nt < 4; nt++)
            #pragma unroll
            for (int i = 0; i < 4; i++) s[m][nt][i] = 0.f;
        #pragma unroll
        for (int kd = 0; kd < 64; kd += 16) {
            uint4 a0 = ldsm4(qfr + (kd << 1));
            uint4 a1 = ldsm4(qfr + ((16 * 72 + kd) << 1));
            #pragma unroll
            for (int nb = 0; nb < 2; ++nb) {
                uint4 bf = ldsm4(kfr + ((nb * 16 * 72 + kd) << 1));
                mma16(s[0][nb * 2],     a0, bf.x, bf.z);
                mma16(s[0][nb * 2 + 1], a0, bf.y, bf.w);
                mma16(s[1][nb * 2],     a1, bf.x, bf.z);
                mma16(s[1][nb * 2 + 1], a1, bf.y, bf.w);
            }
        }

        // exp, mask, normalize; write w (streaming) + stage normalized P
        const int k0 = kt * 64;
        #pragma unroll
        for (int m = 0; m < 2; m++) {
            const int r0g = q0 + wm + m * 16 + g, r1g = r0g + 8;
            #pragma unroll
            for (int nt = 0; nt < 4; nt++) {
                int ck = k0 + wn + nt * 8 + 2 * t;
                float e00 = __expf(s[m][nt][0] * 0.125f) * ivr[m][0]; if (ck     > r0g) e00 = 0.f;
                float e01 = __expf(s[m][nt][1] * 0.125f) * ivr[m][0]; if (ck + 1 > r0g) e01 = 0.f;
                float e10 = __expf(s[m][nt][2] * 0.125f) * ivr[m][1]; if (ck     > r1g) e10 = 0.f;
                float e11 = __expf(s[m][nt][3] * 0.125f) * ivr[m][1]; if (ck + 1 > r1g) e11 = 0.f;
                __stcs((float2*)(wbase + (size_t)r0g * SEQ + ck), make_float2(e00, e01));
                __stcs((float2*)(wbase + (size_t)r1g * SEQ + ck), make_float2(e10, e11));
                int pc = wn + nt * 8 + 2 * t;
                *(uint32_t*)(hs + SP + (wm + m * 16 + g) * 72 + pc)     = pack2(e00, e01);
                *(uint32_t*)(hs + SP + (wm + m * 16 + g + 8) * 72 + pc) = pack2(e10, e11);
            }
        }
        __syncthreads();

        // GEMM2: ctx += P V  (P already normalized)
        #pragma unroll
        for (int kk = 0; kk < 64; kk += 16) {
            uint4 a0 = ldsm4(pfr + (kk << 1));
            uint4 a1 = ldsm4(pfr + ((16 * 72 + kk) << 1));
            #pragma unroll
            for (int nb = 0; nb < 2; ++nb) {
                uint4 bf = ldsm4t(vfr + ((kk * 72 + nb * 16) << 1));
                mma16(cacc[0][nb * 2],     a0, bf.x, bf.y);
                mma16(cacc[0][nb * 2 + 1], a0, bf.z, bf.w);
                mma16(cacc[1][nb * 2],     a1, bf.x, bf.y);
                mma16(cacc[1][nb * 2 + 1], a1, bf.z, bf.w);
            }
        }
    }

    // store ctx (fp16, already normalized) in concat layout [b, s, h*64+d]
    #pragma unroll
    for (int m = 0; m < 2; m++) {
        int r0 = q0 + wm + m * 16 + g;
        #pragma unroll
        for (int nt = 0; nt < 4; nt++) {
            int c = h * HDIM + wn + nt * 8 + 2 * t;
            *(uint32_t*)(ctx + (size_t)(b * SEQ + r0) * DMODEL + c) =
                pack2(cacc[m][nt][0], cacc[m][nt][1]);
            *(uint32_t*)(ctx + (size_t)(b * SEQ + r0 + 8) * DMODEL + c) =
                pack2(cacc[m][nt][2], cacc[m][nt][3]);
        }
    }
}

// ================================================================
// launch
// ================================================================
extern "C" void kernel_launch(void* const* d_in, const int* in_sizes, int n_in,
                              void* d_out, int out_size)
{
    const float* query = (const float*)d_in[0];
    const float* key   = (const float*)d_in[1];
    const float* value = (const float*)d_in[2];
    const float* Wk = (const float*)d_in[4];
    const float* bk = (const float*)d_in[5];
    const float* Wv = (const float*)d_in[6];
    const float* bv = (const float*)d_in[7];
    const float* Wo = (const float*)d_in[8];
    const float* bo = (const float*)d_in[9];

    float* out = (float*)d_out;
    float* w   = out + (size_t)BATCH * SEQ * DMODEL;

    __half *xq, *xk, *xv, *whk, *whv, *who, *qp, *kp, *vp, *ctx;
    cudaGetSymbolAddress((void**)&xq,  g_xq);
    cudaGetSymbolAddress((void**)&xk,  g_xk);
    cudaGetSymbolAddress((void**)&xv,  g_xv);
    cudaGetSymbolAddress((void**)&whk, g_whk);
    cudaGetSymbolAddress((void**)&whv, g_whv);
    cudaGetSymbolAddress((void**)&who, g_who);
    cudaGetSymbolAddress((void**)&qp,  g_qp);
    cudaGetSymbolAddress((void**)&kp,  g_kp);
    cudaGetSymbolAddress((void**)&vp,  g_vp);
    cudaGetSymbolAddress((void**)&ctx, g_ctx);

    cudaFuncSetAttribute(attn_h, cudaFuncAttributeMaxDynamicSharedMemorySize,
                         ATTN_SMEM);
    cudaFuncSetAttribute(gemm_qkv, cudaFuncAttributeMaxDynamicSharedMemorySize,
                         GEMM_SMEM);
    cudaFuncSetAttribute(gemm_o, cudaFuncAttributeMaxDynamicSharedMemorySize,
                         GEMM_SMEM);

    conv_f2h<<<dim3((BATCH * SEQ * DMODEL) / 1024, 3), 256>>>(
        query, key, value, xq, xk, xv);
    conv_f2h<<<dim3((DMODEL * DMODEL) / 1024, 3), 256>>>(
        Wk, Wv, Wo, whk, whv, who);

    gemm_qkv<<<dim3(8, 96), 256, GEMM_SMEM>>>(
        xq, xk, xv, whk, whv, bk, bv, qp, kp, vp);

    attn_h<<<dim3(16, NHEADS, BATCH), 256, ATTN_SMEM>>>(qp, kp, vp, w, ctx);

    gemm_o<<<dim3(8, 32), 256, GEMM_SMEM>>>(ctx, who, bo, out);
}